// round 10
// baseline (speedup 1.0000x reference)
#include <cuda_runtime.h>
#include <cuda_bf16.h>

// XORNet forward: 2-layer LIF spiking net (snntorch Leaky, subtract reset).
// History: R4 = best (16.86us wall; issue 77.8, occ 40.2, regs 64).
//   R6/R7/R8 (FFMA2 variants) all regressed: packed ops hold the fma pipe for
//   2 cycles so pipe work never drops; they only stiffen scheduling.
// R4's true binder: LATENCY (issue 77.8, pipes <=50%, occ 40% capped by
// 64 regs -> 4 CTAs). R9 keeps R4's instruction mix verbatim per lane but
// halves per-thread state: 2 batch elements/thread -> ~46 live regs ->
// __launch_bounds__(256,5) -> 40 warps/SM (62.5% occ) for latency coverage.
//   - x load: exactly one LDG.128 per thread
//   - out store: STG.64, warp-contiguous 256B
// Numerics bit-identical to R4 (rel_err canary = 8.596e-4):
//   m = ((0.9*m) + cur) - s_prev ; s = (m > 1) ; o = k-ascending fma dot.

#define SNN_T 20
#define SNN_H 4

union F2 { float2 f; unsigned long long u; };

__device__ __forceinline__ void mul2(F2& d, const F2& a, const F2& b) {
    asm("mul.rn.f32x2 %0, %1, %2;" : "=l"(d.u) : "l"(a.u), "l"(b.u));
}
__device__ __forceinline__ void add2(F2& d, const F2& a, const F2& b) {
    asm("add.rn.f32x2 %0, %1, %2;" : "=l"(d.u) : "l"(a.u), "l"(b.u));
}
// 1.0f if a > b else 0.0f, single SASS FSET
__device__ __forceinline__ float fset_gt(float a, float b) {
    float r;
    asm("set.gt.f32.f32 %0, %1, %2;" : "=f"(r) : "f"(a), "f"(b));
    return r;
}

__global__ __launch_bounds__(256, 5) void xornet_snn_kernel(
    const float* __restrict__ x,    // [B, 2]
    const float* __restrict__ w1,   // [4, 2]
    const float* __restrict__ w2,   // [1, 4]
    float* __restrict__ out,        // [T, B, 1]
    int B)
{
    const int i = blockIdx.x * blockDim.x + threadIdx.x;  // handles b = 2i, 2i+1
    if (i * 2 >= B) return;
    const int Bh = B >> 1;   // float2 groups per timestep

    // Broadcast weights (L1/L2 hit after first warp).
    float w1r0[SNN_H], w1r1[SNN_H], w2r[SNN_H];
#pragma unroll
    for (int h = 0; h < SNN_H; h++) {
        w1r0[h] = __ldg(&w1[2 * h]);
        w1r1[h] = __ldg(&w1[2 * h + 1]);
        w2r[h]  = __ldg(&w2[h]);
    }

    // x for 2 batch elements: one float4 = {x[2i][0], x[2i][1], x[2i+1][0], x[2i+1][1]}.
    const float4 xa = __ldg(&((const float4*)x)[i]);
    const float x0[2] = {xa.x, xa.z};
    const float x1[2] = {xa.y, xa.w};

    // cur[l][p] packs neurons (2p, 2p+1) for batch lane l (k-ascending fma dot).
    F2 cur[2][2];
#pragma unroll
    for (int l = 0; l < 2; l++)
#pragma unroll
        for (int p = 0; p < 2; p++) {
            cur[l][p].f.x = fmaf(x1[l], w1r1[2 * p],     __fmul_rn(x0[l], w1r0[2 * p]));
            cur[l][p].f.y = fmaf(x1[l], w1r1[2 * p + 1], __fmul_rn(x0[l], w1r0[2 * p + 1]));
        }

    // State: membranes packed per neuron-pair, spikes scalar; 2 independent lanes.
    F2 m1[2][2];
    float s1[2][SNN_H];
    float m2[2], s2[2];
#pragma unroll
    for (int l = 0; l < 2; l++) {
        m2[l] = 0.0f; s2[l] = 0.0f;
#pragma unroll
        for (int p = 0; p < 2; p++) m1[l][p].u = 0ull;
#pragma unroll
        for (int h = 0; h < SNN_H; h++) s1[l][h] = 0.0f;
    }

    float2* outp = (float2*)out + i;

#pragma unroll
    for (int t = 0; t < SNN_T; t++) {
#pragma unroll
        for (int l = 0; l < 2; l++) {
#pragma unroll
            for (int p = 0; p < 2; p++) {
                F2 mm;
                mul2(mm, m1[l][p], F2{ .f = make_float2(0.9f, 0.9f) });  // 0.9*m
                add2(mm, mm, cur[l][p]);                                 // + cur
                // - reset (prev spike): FFMA-imm == __fsub_rn(m,s) for s in {0,1}
                mm.f.x = fmaf(s1[l][2 * p],     -1.0f, mm.f.x);
                mm.f.y = fmaf(s1[l][2 * p + 1], -1.0f, mm.f.y);
                m1[l][p] = mm;
                s1[l][2 * p]     = fset_gt(mm.f.x, 1.0f);   // spike = (m > 1)
                s1[l][2 * p + 1] = fset_gt(mm.f.y, 1.0f);
            }
        }
        float2 ov;
#pragma unroll
        for (int l = 0; l < 2; l++) {
            // spk1 @ w2^T: binary s -> exact products, k-ascending fma chain.
            float oo = __fmul_rn(s1[l][0], w2r[0]);
            oo = fmaf(s1[l][1], w2r[1], oo);
            oo = fmaf(s1[l][2], w2r[2], oo);
            oo = fmaf(s1[l][3], w2r[3], oo);
            // layer-2 LIF (scalar, same order as reference)
            float mm2 = __fmul_rn(0.9f, m2[l]);
            mm2 = __fadd_rn(mm2, oo);
            mm2 = fmaf(s2[l], -1.0f, mm2);
            m2[l] = mm2;
            s2[l] = fset_gt(mm2, 1.0f);
            (l == 0 ? ov.x : ov.y) = s2[l];
        }
        *outp = ov;                  // warp-coalesced STG.64 (256B/warp)
        outp += Bh;
    }
}

extern "C" void kernel_launch(void* const* d_in, const int* in_sizes, int n_in,
                              void* d_out, int out_size)
{
    const float* x  = (const float*)d_in[0];   // [B, 2]
    const float* w1 = (const float*)d_in[1];   // [4, 2]
    const float* w2 = (const float*)d_in[2];   // [1, 4]
    float* out = (float*)d_out;                // [T, B, 1]

    const int B = in_sizes[0] / 2;             // 1,048,576
    const int threads = 256;
    const int nthreads = B / 2;                // one thread per 2 batch elems
    const int blocks = (nthreads + threads - 1) / threads;

    xornet_snn_kernel<<<blocks, threads>>>(x, w1, w2, out, B);
}

// round 11
// speedup vs baseline: 1.0017x; 1.0017x over previous
#include <cuda_runtime.h>
#include <cuda_bf16.h>

// XORNet forward: 2-layer LIF spiking net (snntorch Leaky, subtract reset).
// Final model after R6-R9 ablations: this kernel is instruction-throughput
// bound at ~78% issue (1.34e7 warp-instr vs 1.78e7 slot capacity), and:
//   - FFMA2/packed-op variants (R6,R7,R8) all lose: packed ops hold the fma
//     pipe 2 cycles (no pipe-work saved) and stiffen register pairing.
//   - Higher occupancy (R9, 52%) does not raise issue; smaller elems/thread
//     raises store-issue cost (STG.64 3.9 cyc/elem vs STG.128 3.0).
// So this is R4 -- the measured 16.86us best -- re-landed verbatim, plus:
//   - __launch_bounds__(256,4): pin the 64-reg / 4-CTA operating point.
//   - pointer-increment store addressing (IADD3 instead of per-store IMAD).
// Per-neuron-step slots are at the floor: packed mul/add shared per neuron
// pair + scalar FFMA-imm reset + FSET spike = 3 slots/neuron.
// Numerics: exact reference rounding chain, rel_err canary = 8.596e-4:
//   m = ((0.9*m) + cur) - s_prev ; s = (m > 1) ; o = k-ascending fma dot.

#define SNN_T 20
#define SNN_H 4

union F2 { float2 f; unsigned long long u; };

__device__ __forceinline__ void mul2(F2& d, const F2& a, const F2& b) {
    asm("mul.rn.f32x2 %0, %1, %2;" : "=l"(d.u) : "l"(a.u), "l"(b.u));
}
__device__ __forceinline__ void add2(F2& d, const F2& a, const F2& b) {
    asm("add.rn.f32x2 %0, %1, %2;" : "=l"(d.u) : "l"(a.u), "l"(b.u));
}
// 1.0f if a > b else 0.0f, single SASS FSET
__device__ __forceinline__ float fset_gt(float a, float b) {
    float r;
    asm("set.gt.f32.f32 %0, %1, %2;" : "=f"(r) : "f"(a), "f"(b));
    return r;
}

__global__ __launch_bounds__(256, 4) void xornet_snn_kernel(
    const float* __restrict__ x,    // [B, 2]
    const float* __restrict__ w1,   // [4, 2]
    const float* __restrict__ w2,   // [1, 4]
    float* __restrict__ out,        // [T, B, 1]
    int B)
{
    const int i = blockIdx.x * blockDim.x + threadIdx.x;  // handles b = 4i..4i+3
    if (i * 4 >= B) return;
    const int Bq = B >> 2;

    // Broadcast weights (L2/L1 hit after first warp).
    float w1r0[SNN_H], w1r1[SNN_H], w2r[SNN_H];
#pragma unroll
    for (int h = 0; h < SNN_H; h++) {
        w1r0[h] = __ldg(&w1[2 * h]);
        w1r1[h] = __ldg(&w1[2 * h + 1]);
        w2r[h]  = __ldg(&w2[h]);
    }

    // x for 4 batch elements: 2x float4.
    const float4 xa = __ldg(&((const float4*)x)[2 * i]);
    const float4 xb = __ldg(&((const float4*)x)[2 * i + 1]);
    const float x0[4] = {xa.x, xa.z, xb.x, xb.z};
    const float x1[4] = {xa.y, xa.w, xb.y, xb.w};

    // cur[l][p] packs neurons (2p, 2p+1) for batch lane l (k-ascending fma dot).
    F2 cur[4][2];
#pragma unroll
    for (int l = 0; l < 4; l++)
#pragma unroll
        for (int p = 0; p < 2; p++) {
            cur[l][p].f.x = fmaf(x1[l], w1r1[2 * p],     __fmul_rn(x0[l], w1r0[2 * p]));
            cur[l][p].f.y = fmaf(x1[l], w1r1[2 * p + 1], __fmul_rn(x0[l], w1r0[2 * p + 1]));
        }

    F2 c09; c09.f = make_float2(0.9f, 0.9f);

    // State: membranes packed per neuron-pair, spikes scalar; 4 independent lanes.
    F2 m1[4][2];
    float s1[4][SNN_H];
    F2 m2p[2];        // layer-2 membranes, batch-lane pairs (0,1) and (2,3)
    float s2[4];
#pragma unroll
    for (int l = 0; l < 4; l++) {
        s2[l] = 0.0f;
#pragma unroll
        for (int p = 0; p < 2; p++) { m1[l][p].u = 0ull; }
#pragma unroll
        for (int h = 0; h < SNN_H; h++) s1[l][h] = 0.0f;
    }
    m2p[0].u = 0ull; m2p[1].u = 0ull;

    float4* outp = (float4*)out + i;

#pragma unroll
    for (int t = 0; t < SNN_T; t++) {
        float o[4];
#pragma unroll
        for (int l = 0; l < 4; l++) {
#pragma unroll
            for (int p = 0; p < 2; p++) {
                F2 mm;
                mul2(mm, m1[l][p], c09);           // 0.9*m   (packed RN)
                add2(mm, mm, cur[l][p]);           // + cur   (packed RN)
                // - reset (prev spike): FFMA-imm == __fsub_rn(m, s) for s in {0,1}
                mm.f.x = fmaf(s1[l][2 * p],     -1.0f, mm.f.x);
                mm.f.y = fmaf(s1[l][2 * p + 1], -1.0f, mm.f.y);
                m1[l][p] = mm;
                // spike = (m > 1) as 1.0f/0.0f, single FSET
                s1[l][2 * p]     = fset_gt(mm.f.x, 1.0f);
                s1[l][2 * p + 1] = fset_gt(mm.f.y, 1.0f);
            }
            // spk1 @ w2^T: binary s -> exact products, k-ascending fma chain.
            float oo = __fmul_rn(s1[l][0], w2r[0]);
            oo = fmaf(s1[l][1], w2r[1], oo);
            oo = fmaf(s1[l][2], w2r[2], oo);
            oo = fmaf(s1[l][3], w2r[3], oo);
            o[l] = oo;
        }
        // layer-2 LIF, packed across batch-lane pairs
#pragma unroll
        for (int q = 0; q < 2; q++) {
            F2 op; op.f = make_float2(o[2 * q], o[2 * q + 1]);
            F2 mm;
            mul2(mm, m2p[q], c09);
            add2(mm, mm, op);
            mm.f.x = fmaf(s2[2 * q],     -1.0f, mm.f.x);
            mm.f.y = fmaf(s2[2 * q + 1], -1.0f, mm.f.y);
            m2p[q] = mm;
            s2[2 * q]     = fset_gt(mm.f.x, 1.0f);
            s2[2 * q + 1] = fset_gt(mm.f.y, 1.0f);
        }
        float4 ov;
        ov.x = s2[0]; ov.y = s2[1]; ov.z = s2[2]; ov.w = s2[3];
        *outp = ov;                  // warp-coalesced STG.128
        outp += Bq;                  // strength-reduced addressing (IADD3)
    }
}

extern "C" void kernel_launch(void* const* d_in, const int* in_sizes, int n_in,
                              void* d_out, int out_size)
{
    const float* x  = (const float*)d_in[0];   // [B, 2]
    const float* w1 = (const float*)d_in[1];   // [4, 2]
    const float* w2 = (const float*)d_in[2];   // [1, 4]
    float* out = (float*)d_out;                // [T, B, 1]

    const int B = in_sizes[0] / 2;             // 1,048,576
    const int threads = 256;
    const int nthreads = B / 4;                // one thread per 4 batch elems
    const int blocks = (nthreads + threads - 1) / threads;

    xornet_snn_kernel<<<blocks, threads>>>(x, w1, w2, out, B);
}

// round 12
// speedup vs baseline: 1.0169x; 1.0153x over previous
#include <cuda_runtime.h>
#include <cuda_bf16.h>

// XORNet forward: 2-layer LIF spiking net (snntorch Leaky, subtract reset).
// Model after R6-R10 ablations: instruction-throughput bound at ~78% issue;
// all packed-op / occupancy / persistent variants lose. Two residual losses:
//   (a) R10's pointer-increment stores broke R4's immediate-offset STG form
//       (15.78 -> 17.15us ncu). Fix: indexed stores, fully unrolled T.
//   (b) Wave quantization: 1024 CTAs over 592 resident = 1.73 waves = 86.5%
//       utilization. Fix: heterogeneous static split -- wave 1 = 592 CTAs x
//       4 elems/thread (R4 body verbatim), wave 2 = 592 CTAs x <=3 elems
//       (coalesced float2 pair + predicated single). Wave-2 threads do ~0.64x
//       the work -> total ~1.64 T_unit vs 2.0 today.
// Numerics: identical per-element rounding chain everywhere
//   m = ((0.9*m) + cur) - s_prev ; s = (m > 1) ; o = k-ascending fma dot.
// rel_err canary = 8.596e-4.

#define SNN_T 20
#define SNN_H 4

// Split constants for B = 1048576, 256 thr/block, 64 regs -> 592 resident CTAs
#define W1_CTAS   592
#define W1_ELEMS  606208      // 592*256*4
#define PAIR_F4   303104      // x float4 index base for wave-2 pairs (=W1_ELEMS/2)
#define SINGLE_B  909312      // first elem of wave-2 singles (=W1_ELEMS+2*151552)
#define N_SINGLE  139264      // number of single elems (=B-SINGLE_B)

union F2 { float2 f; unsigned long long u; };

__device__ __forceinline__ void mul2(F2& d, const F2& a, const F2& b) {
    asm("mul.rn.f32x2 %0, %1, %2;" : "=l"(d.u) : "l"(a.u), "l"(b.u));
}
__device__ __forceinline__ void add2(F2& d, const F2& a, const F2& b) {
    asm("add.rn.f32x2 %0, %1, %2;" : "=l"(d.u) : "l"(a.u), "l"(b.u));
}
// 1.0f if a > b else 0.0f, single SASS FSET
__device__ __forceinline__ float fset_gt(float a, float b) {
    float r;
    asm("set.gt.f32.f32 %0, %1, %2;" : "=f"(r) : "f"(a), "f"(b));
    return r;
}

__global__ __launch_bounds__(256, 4) void xornet_snn_split(
    const float* __restrict__ x,    // [B, 2]
    const float* __restrict__ w1,   // [4, 2]
    const float* __restrict__ w2,   // [1, 4]
    float* __restrict__ out,        // [T, B, 1]
    int B)
{
    // Broadcast weights (L2/L1 hit after first warp).
    float w1r0[SNN_H], w1r1[SNN_H], w2r[SNN_H];
#pragma unroll
    for (int h = 0; h < SNN_H; h++) {
        w1r0[h] = __ldg(&w1[2 * h]);
        w1r1[h] = __ldg(&w1[2 * h + 1]);
        w2r[h]  = __ldg(&w2[h]);
    }
    F2 c09; c09.f = make_float2(0.9f, 0.9f);

    if (blockIdx.x < W1_CTAS) {
        // ─── Wave 1: R4 body verbatim — 4 elems/thread, immediate-offset stores ───
        const int i = blockIdx.x * blockDim.x + threadIdx.x;   // b = 4i..4i+3
        const int Bq = B >> 2;

        const float4 xa = __ldg(&((const float4*)x)[2 * i]);
        const float4 xb = __ldg(&((const float4*)x)[2 * i + 1]);
        const float x0[4] = {xa.x, xa.z, xb.x, xb.z};
        const float x1[4] = {xa.y, xa.w, xb.y, xb.w};

        F2 cur[4][2];
#pragma unroll
        for (int l = 0; l < 4; l++)
#pragma unroll
            for (int p = 0; p < 2; p++) {
                cur[l][p].f.x = fmaf(x1[l], w1r1[2 * p],     __fmul_rn(x0[l], w1r0[2 * p]));
                cur[l][p].f.y = fmaf(x1[l], w1r1[2 * p + 1], __fmul_rn(x0[l], w1r0[2 * p + 1]));
            }

        F2 m1[4][2];
        float s1[4][SNN_H];
        F2 m2p[2];
        float s2[4];
#pragma unroll
        for (int l = 0; l < 4; l++) {
            s2[l] = 0.0f;
#pragma unroll
            for (int p = 0; p < 2; p++) m1[l][p].u = 0ull;
#pragma unroll
            for (int h = 0; h < SNN_H; h++) s1[l][h] = 0.0f;
        }
        m2p[0].u = 0ull; m2p[1].u = 0ull;

#pragma unroll
        for (int t = 0; t < SNN_T; t++) {
            float o[4];
#pragma unroll
            for (int l = 0; l < 4; l++) {
#pragma unroll
                for (int p = 0; p < 2; p++) {
                    F2 mm;
                    mul2(mm, m1[l][p], c09);           // 0.9*m
                    add2(mm, mm, cur[l][p]);           // + cur
                    mm.f.x = fmaf(s1[l][2 * p],     -1.0f, mm.f.x);   // - reset
                    mm.f.y = fmaf(s1[l][2 * p + 1], -1.0f, mm.f.y);
                    m1[l][p] = mm;
                    s1[l][2 * p]     = fset_gt(mm.f.x, 1.0f);
                    s1[l][2 * p + 1] = fset_gt(mm.f.y, 1.0f);
                }
                float oo = __fmul_rn(s1[l][0], w2r[0]);
                oo = fmaf(s1[l][1], w2r[1], oo);
                oo = fmaf(s1[l][2], w2r[2], oo);
                oo = fmaf(s1[l][3], w2r[3], oo);
                o[l] = oo;
            }
#pragma unroll
            for (int q = 0; q < 2; q++) {
                F2 op; op.f = make_float2(o[2 * q], o[2 * q + 1]);
                F2 mm;
                mul2(mm, m2p[q], c09);
                add2(mm, mm, op);
                mm.f.x = fmaf(s2[2 * q],     -1.0f, mm.f.x);
                mm.f.y = fmaf(s2[2 * q + 1], -1.0f, mm.f.y);
                m2p[q] = mm;
                s2[2 * q]     = fset_gt(mm.f.x, 1.0f);
                s2[2 * q + 1] = fset_gt(mm.f.y, 1.0f);
            }
            float4 ov;
            ov.x = s2[0]; ov.y = s2[1]; ov.z = s2[2]; ov.w = s2[3];
            ((float4*)out)[t * Bq + i] = ov;   // immediate-offset STG.128
        }
    } else {
        // ─── Wave 2: <=3 elems/thread (pair + predicated single) ───
        const int g = (blockIdx.x - W1_CTAS) * blockDim.x + threadIdx.x; // 0..151551
        const int Bh = B >> 1;

        // pair elems: b = W1_ELEMS + 2g, W1_ELEMS + 2g + 1  (x = one float4)
        const float4 xa = __ldg(&((const float4*)x)[PAIR_F4 + g]);
        const float px0[2] = {xa.x, xa.z};
        const float px1[2] = {xa.y, xa.w};
        // single elem: b = SINGLE_B + g (clamped; store predicated)
        const bool v3 = (g < N_SINGLE);
        const int e2 = v3 ? (SINGLE_B + g) : (B - 1);
        const float2 xc = __ldg(&((const float2*)x)[e2]);

        F2 cur[2][2], curc[2];
#pragma unroll
        for (int p = 0; p < 2; p++) {
#pragma unroll
            for (int l = 0; l < 2; l++) {
                cur[l][p].f.x = fmaf(px1[l], w1r1[2 * p],     __fmul_rn(px0[l], w1r0[2 * p]));
                cur[l][p].f.y = fmaf(px1[l], w1r1[2 * p + 1], __fmul_rn(px0[l], w1r0[2 * p + 1]));
            }
            curc[p].f.x = fmaf(xc.y, w1r1[2 * p],     __fmul_rn(xc.x, w1r0[2 * p]));
            curc[p].f.y = fmaf(xc.y, w1r1[2 * p + 1], __fmul_rn(xc.x, w1r0[2 * p + 1]));
        }

        F2 m1[2][2], m1c[2];
        float s1[2][SNN_H], s1c[SNN_H];
        F2 m2p;            // layer-2 packed across the 2 pair lanes
        float s2[2], m2c, s2c;
#pragma unroll
        for (int l = 0; l < 2; l++) {
            s2[l] = 0.0f;
#pragma unroll
            for (int p = 0; p < 2; p++) m1[l][p].u = 0ull;
#pragma unroll
            for (int h = 0; h < SNN_H; h++) s1[l][h] = 0.0f;
        }
        m1c[0].u = 0ull; m1c[1].u = 0ull;
#pragma unroll
        for (int h = 0; h < SNN_H; h++) s1c[h] = 0.0f;
        m2p.u = 0ull; m2c = 0.0f; s2c = 0.0f;

#pragma unroll
        for (int t = 0; t < SNN_T; t++) {
            float o[2];
#pragma unroll
            for (int l = 0; l < 2; l++) {
#pragma unroll
                for (int p = 0; p < 2; p++) {
                    F2 mm;
                    mul2(mm, m1[l][p], c09);
                    add2(mm, mm, cur[l][p]);
                    mm.f.x = fmaf(s1[l][2 * p],     -1.0f, mm.f.x);
                    mm.f.y = fmaf(s1[l][2 * p + 1], -1.0f, mm.f.y);
                    m1[l][p] = mm;
                    s1[l][2 * p]     = fset_gt(mm.f.x, 1.0f);
                    s1[l][2 * p + 1] = fset_gt(mm.f.y, 1.0f);
                }
                float oo = __fmul_rn(s1[l][0], w2r[0]);
                oo = fmaf(s1[l][1], w2r[1], oo);
                oo = fmaf(s1[l][2], w2r[2], oo);
                oo = fmaf(s1[l][3], w2r[3], oo);
                o[l] = oo;
            }
            {   // pair layer-2 (packed)
                F2 op; op.f = make_float2(o[0], o[1]);
                F2 mm;
                mul2(mm, m2p, c09);
                add2(mm, mm, op);
                mm.f.x = fmaf(s2[0], -1.0f, mm.f.x);
                mm.f.y = fmaf(s2[1], -1.0f, mm.f.y);
                m2p = mm;
                s2[0] = fset_gt(mm.f.x, 1.0f);
                s2[1] = fset_gt(mm.f.y, 1.0f);
            }
            {   // single lane
#pragma unroll
                for (int p = 0; p < 2; p++) {
                    F2 mm;
                    mul2(mm, m1c[p], c09);
                    add2(mm, mm, curc[p]);
                    mm.f.x = fmaf(s1c[2 * p],     -1.0f, mm.f.x);
                    mm.f.y = fmaf(s1c[2 * p + 1], -1.0f, mm.f.y);
                    m1c[p] = mm;
                    s1c[2 * p]     = fset_gt(mm.f.x, 1.0f);
                    s1c[2 * p + 1] = fset_gt(mm.f.y, 1.0f);
                }
                float oo = __fmul_rn(s1c[0], w2r[0]);
                oo = fmaf(s1c[1], w2r[1], oo);
                oo = fmaf(s1c[2], w2r[2], oo);
                oo = fmaf(s1c[3], w2r[3], oo);
                float mm2 = __fmul_rn(0.9f, m2c);
                mm2 = __fadd_rn(mm2, oo);
                mm2 = fmaf(s2c, -1.0f, mm2);
                m2c = mm2;
                s2c = fset_gt(mm2, 1.0f);
            }
            float2 pv; pv.x = s2[0]; pv.y = s2[1];
            ((float2*)out)[t * Bh + PAIR_F4 + g] = pv;          // coalesced STG.64
            if (v3) out[t * B + SINGLE_B + g] = s2c;            // coalesced STG.32
        }
    }
}

// Generic fallback (R4) for unexpected B.
__global__ __launch_bounds__(256, 4) void xornet_snn_plain(
    const float* __restrict__ x, const float* __restrict__ w1,
    const float* __restrict__ w2, float* __restrict__ out, int B)
{
    const int i = blockIdx.x * blockDim.x + threadIdx.x;
    if (i * 4 >= B) return;
    const int Bq = B >> 2;
    float w1r0[SNN_H], w1r1[SNN_H], w2r[SNN_H];
#pragma unroll
    for (int h = 0; h < SNN_H; h++) {
        w1r0[h] = __ldg(&w1[2 * h]);
        w1r1[h] = __ldg(&w1[2 * h + 1]);
        w2r[h]  = __ldg(&w2[h]);
    }
    F2 c09; c09.f = make_float2(0.9f, 0.9f);
    const float4 xa = __ldg(&((const float4*)x)[2 * i]);
    const float4 xb = __ldg(&((const float4*)x)[2 * i + 1]);
    const float x0[4] = {xa.x, xa.z, xb.x, xb.z};
    const float x1[4] = {xa.y, xa.w, xb.y, xb.w};
    F2 cur[4][2];
#pragma unroll
    for (int l = 0; l < 4; l++)
#pragma unroll
        for (int p = 0; p < 2; p++) {
            cur[l][p].f.x = fmaf(x1[l], w1r1[2 * p],     __fmul_rn(x0[l], w1r0[2 * p]));
            cur[l][p].f.y = fmaf(x1[l], w1r1[2 * p + 1], __fmul_rn(x0[l], w1r0[2 * p + 1]));
        }
    F2 m1[4][2];
    float s1[4][SNN_H];
    F2 m2p[2];
    float s2[4];
#pragma unroll
    for (int l = 0; l < 4; l++) {
        s2[l] = 0.0f;
#pragma unroll
        for (int p = 0; p < 2; p++) m1[l][p].u = 0ull;
#pragma unroll
        for (int h = 0; h < SNN_H; h++) s1[l][h] = 0.0f;
    }
    m2p[0].u = 0ull; m2p[1].u = 0ull;
#pragma unroll
    for (int t = 0; t < SNN_T; t++) {
        float o[4];
#pragma unroll
        for (int l = 0; l < 4; l++) {
#pragma unroll
            for (int p = 0; p < 2; p++) {
                F2 mm;
                mul2(mm, m1[l][p], c09);
                add2(mm, mm, cur[l][p]);
                mm.f.x = fmaf(s1[l][2 * p],     -1.0f, mm.f.x);
                mm.f.y = fmaf(s1[l][2 * p + 1], -1.0f, mm.f.y);
                m1[l][p] = mm;
                s1[l][2 * p]     = fset_gt(mm.f.x, 1.0f);
                s1[l][2 * p + 1] = fset_gt(mm.f.y, 1.0f);
            }
            float oo = __fmul_rn(s1[l][0], w2r[0]);
            oo = fmaf(s1[l][1], w2r[1], oo);
            oo = fmaf(s1[l][2], w2r[2], oo);
            oo = fmaf(s1[l][3], w2r[3], oo);
            o[l] = oo;
        }
#pragma unroll
        for (int q = 0; q < 2; q++) {
            F2 op; op.f = make_float2(o[2 * q], o[2 * q + 1]);
            F2 mm;
            mul2(mm, m2p[q], c09);
            add2(mm, mm, op);
            mm.f.x = fmaf(s2[2 * q],     -1.0f, mm.f.x);
            mm.f.y = fmaf(s2[2 * q + 1], -1.0f, mm.f.y);
            m2p[q] = mm;
            s2[2 * q]     = fset_gt(mm.f.x, 1.0f);
            s2[2 * q + 1] = fset_gt(mm.f.y, 1.0f);
        }
        float4 ov;
        ov.x = s2[0]; ov.y = s2[1]; ov.z = s2[2]; ov.w = s2[3];
        ((float4*)out)[t * Bq + i] = ov;
    }
}

extern "C" void kernel_launch(void* const* d_in, const int* in_sizes, int n_in,
                              void* d_out, int out_size)
{
    const float* x  = (const float*)d_in[0];   // [B, 2]
    const float* w1 = (const float*)d_in[1];   // [4, 2]
    const float* w2 = (const float*)d_in[2];   // [1, 4]
    float* out = (float*)d_out;                // [T, B, 1]

    const int B = in_sizes[0] / 2;
    if (B == 1048576) {
        // wave-balanced split: 592 CTAs @ 4 elems + 592 CTAs @ <=3 elems
        xornet_snn_split<<<2 * W1_CTAS, 256>>>(x, w1, w2, out, B);
    } else {
        const int blocks = (B / 4 + 255) / 256;
        xornet_snn_plain<<<blocks, 256>>>(x, w1, w2, out, B);
    }
}